// round 10
// baseline (speedup 1.0000x reference)
#include <cuda_runtime.h>

// Row-wise normalization: out[r, :] = in[r, :] / sum(in[r, :])
// Rows = 2*32*1024 = 65536, row length = 1024 floats = 256 float4.
//
// Flat grid, TWO warps per row, TWO rows per warp-pair per barrier:
//  - each warp front-batches 8 independent LDG.128 (4 for its half of row A,
//    4 for its half of row B)  -> 4 KB in flight per warp in load phase
//  - ONE named 64-thread barrier exchanges both rows' partial sums
//    (pairwise: no block-wide sync coupling other rows)
//  - regs ~50 -> 5 blocks/SM; in-flight bytes per SM ~= 2x R9
__global__ void __launch_bounds__(256, 5)
normalizer_kernel(const float4* __restrict__ in, float4* __restrict__ out) {
    const unsigned tid  = threadIdx.x;
    const unsigned w    = tid >> 5;          // warp 0..7
    const unsigned lane = tid & 31u;
    const unsigned pair = w >> 1;            // row-pair group 0..3
    const unsigned half = w & 1u;            // which half of each row
    const unsigned rowA = blockIdx.x * 8u + pair * 2u;   // rows rowA, rowA+1

    const size_t baseA = (size_t)rowA * 256u + half * 128u + lane;
    const size_t baseB = baseA + 256u;       // row rowA+1, same half/lane

    const float4* __restrict__ rpA = in + baseA;
    const float4* __restrict__ rpB = in + baseB;

    // Front-batch all 8 loads: MLP = 8 independent LDG.128
    float4 a[4], b[4];
    #pragma unroll
    for (int k = 0; k < 4; k++) a[k] = __ldcs(rpA + 32 * k);
    #pragma unroll
    for (int k = 0; k < 4; k++) b[k] = __ldcs(rpB + 32 * k);

    float sA = 0.0f, sB = 0.0f;
    #pragma unroll
    for (int k = 0; k < 4; k++) {
        sA += (a[k].x + a[k].y) + (a[k].z + a[k].w);
        sB += (b[k].x + b[k].y) + (b[k].z + b[k].w);
    }

    #pragma unroll
    for (int off = 16; off > 0; off >>= 1) {
        sA += __shfl_xor_sync(0xffffffffu, sA, off);
        sB += __shfl_xor_sync(0xffffffffu, sB, off);
    }

    // One pairwise barrier exchanges BOTH rows' partials
    __shared__ float partA[8], partB[8];
    if (lane == 0) { partA[w] = sA; partB[w] = sB; }
    asm volatile("bar.sync %0, 64;" :: "r"(pair + 1) : "memory");

    const float degA = partA[pair * 2] + partA[pair * 2 + 1];
    const float degB = partB[pair * 2] + partB[pair * 2 + 1];

    float invA = 1.0f / degA;
    float invB = 1.0f / degB;
    if (!isfinite(invA)) invA = 0.0f;        // reference: remove_nan_inf
    if (!isfinite(invB)) invB = 0.0f;

    float4* __restrict__ wpA = out + baseA;
    float4* __restrict__ wpB = out + baseB;
    #pragma unroll
    for (int k = 0; k < 4; k++) {
        float4 t = a[k];
        t.x *= invA; t.y *= invA; t.z *= invA; t.w *= invA;
        __stcs(wpA + 32 * k, t);
    }
    #pragma unroll
    for (int k = 0; k < 4; k++) {
        float4 t = b[k];
        t.x *= invB; t.y *= invB; t.z *= invB; t.w *= invB;
        __stcs(wpB + 32 * k, t);
    }
}

extern "C" void kernel_launch(void* const* d_in, const int* in_sizes, int n_in,
                              void* d_out, int out_size) {
    (void)in_sizes; (void)n_in; (void)out_size;
    const float4* in  = (const float4*)d_in[0];
    float4*       out = (float4*)d_out;

    // 65536 rows, 8 rows per block -> 8192 blocks
    normalizer_kernel<<<65536 / 8, 256>>>(in, out);
}

// round 11
// speedup vs baseline: 1.0163x; 1.0163x over previous
#include <cuda_runtime.h>

// Row-wise normalization: out[r, :] = in[r, :] / sum(in[r, :])
// Rows = 2*32*1024 = 65536, row length = 1024 floats = 256 float4.
//
// Best-wall configuration (R9) + last-use load policy:
//  - TWO warps per row, 4 float4 per lane, ~31 regs -> 8 blocks/SM
//  - __ldlu loads: each byte is read exactly once, .lu evicts-on-read so
//    the L1 pass-through path drains faster than .cs streaming retention
//  - pairwise named barrier (bar.sync id, 64): each row's warp pair syncs
//    only with itself, no block-wide coupling
//  - .cs streaming stores (no reuse, skip L2 retention)
__global__ void __launch_bounds__(256, 8)
normalizer_kernel(const float4* __restrict__ in, float4* __restrict__ out) {
    const unsigned tid  = threadIdx.x;
    const unsigned w    = tid >> 5;          // warp 0..7
    const unsigned lane = tid & 31u;
    const unsigned pair = w >> 1;            // row-pair 0..3
    const unsigned half = w & 1u;            // which half of the row
    const unsigned row  = blockIdx.x * 4u + pair;

    const size_t base = (size_t)row * 256u + half * 128u + lane;
    const float4* __restrict__ rp = in  + base;
    float4*       __restrict__ wp = out + base;

    float4 v[4];
    #pragma unroll
    for (int k = 0; k < 4; k++)
        v[k] = __ldlu(rp + 32 * k);          // 4 independent LDG.128, last-use

    float s = 0.0f;
    #pragma unroll
    for (int k = 0; k < 4; k++)
        s += (v[k].x + v[k].y) + (v[k].z + v[k].w);

    #pragma unroll
    for (int off = 16; off > 0; off >>= 1)
        s += __shfl_xor_sync(0xffffffffu, s, off);

    // Pairwise cross-warp reduce: 2-float smem exchange + 64-thread barrier
    __shared__ float part[8];
    if (lane == 0) part[w] = s;
    asm volatile("bar.sync %0, 64;" :: "r"(pair + 1) : "memory");
    const float deg = part[pair * 2] + part[pair * 2 + 1];

    float inv = 1.0f / deg;
    if (!isfinite(inv)) inv = 0.0f;          // reference: remove_nan_inf

    #pragma unroll
    for (int k = 0; k < 4; k++) {
        float4 t = v[k];
        t.x *= inv; t.y *= inv; t.z *= inv; t.w *= inv;
        __stcs(wp + 32 * k, t);
    }
}

extern "C" void kernel_launch(void* const* d_in, const int* in_sizes, int n_in,
                              void* d_out, int out_size) {
    (void)in_sizes; (void)n_in; (void)out_size;
    const float4* in  = (const float4*)d_in[0];
    float4*       out = (float4*)d_out;

    // 65536 rows, 4 rows per block -> 16384 blocks
    normalizer_kernel<<<65536 / 4, 256>>>(in, out);
}